// round 10
// baseline (speedup 1.0000x reference)
#include <cuda_runtime.h>

#define NPTS  4096
#define NCTA  128
#define TPB   512
#define IPC   32          // i-points per CTA
#define NSL   64          // j-slices (64 j each)
#define JPS   (NPTS/NSL)  // 64
#define STEPS 10
#define NSIT  10          // Newton-Schulz iterations

// shared memory layout (bytes)
#define SM_SJ    0                       // float4[4096]  = 65536
#define SM_KEY   (NPTS*16)               // u64[NSL][32]  = 16384
#define SM_MYPC  (SM_KEY + NSL*32*8)     // float[96]
#define SM_MYP1  (SM_MYPC + 96*4)        // float[96]
#define SM_SRT   (SM_MYP1 + 96*4)        // float[12] (+pad)
#define SM_SRED  (SM_SRT + 16*4)         // float[4][15]
#define SM_TOTAL (SM_SRED + 4*15*4 + 64)

// global scratch (no allocations allowed)
// Per-iteration, per-CTA 128B arrival line: [0..14] partials, [15] tag (int 1).
__device__ float g_arr[STEPS+1][NCTA][32];
__device__ float g_RT[12];
__device__ int   g_sync[64];   // [48] release flag (k+1)

__device__ __forceinline__ unsigned int fkey(float f) {
    unsigned int u = __float_as_uint(f);
    return (u & 0x80000000u) ? ~u : (u | 0x80000000u);
}

// ---------------------------------------------------------------------------
// Newton-Schulz polar: Q = orthogonal polar factor of M (3x3, det(M)>0).
// ---------------------------------------------------------------------------
__device__ __forceinline__ void polar3(const float M[9], float Q[9])
{
    float f2 = 0.f;
    #pragma unroll
    for (int q = 0; q < 9; q++) f2 = fmaf(M[q], M[q], f2);
    float inv = rsqrtf(f2);
    float X[9];
    #pragma unroll
    for (int q = 0; q < 9; q++) X[q] = M[q]*inv;

    #pragma unroll
    for (int it = 0; it < NSIT; it++) {
        float W[9];   // W = X^T X
        #pragma unroll
        for (int i = 0; i < 3; i++)
            #pragma unroll
            for (int j = 0; j < 3; j++)
                W[3*i+j] = fmaf(X[0+i], X[0+j],
                           fmaf(X[3+i], X[3+j], X[6+i]*X[6+j]));
        float Y[9];   // Y = X W
        #pragma unroll
        for (int i = 0; i < 3; i++)
            #pragma unroll
            for (int j = 0; j < 3; j++)
                Y[3*i+j] = fmaf(X[3*i+0], W[0+j],
                           fmaf(X[3*i+1], W[3+j], X[3*i+2]*W[6+j]));
        #pragma unroll
        for (int q = 0; q < 9; q++) X[q] = fmaf(1.5f, X[q], -0.5f*Y[q]);
    }
    #pragma unroll
    for (int q = 0; q < 9; q++) Q[q] = X[q];
}

// warp-reduce 15 accumulators (full warp, fixed order -> deterministic)
__device__ __forceinline__ void wred15(float a[15]) {
    #pragma unroll
    for (int q = 0; q < 15; q++)
        #pragma unroll
        for (int off = 16; off; off >>= 1)
            a[q] += __shfl_down_sync(0xffffffffu, a[q], off);
}

// solve from reduced sums (sred[4][15] in smem) -> R[9], t[3]
__device__ __forceinline__ void solve_from_sred(const float* sred,
                                                float R[9], float t[3])
{
    float s15[15];
    #pragma unroll
    for (int q = 0; q < 15; q++)
        s15[q] = (sred[q] + sred[15+q]) + (sred[30+q] + sred[45+q]);
    const float invN = 1.0f/NPTS;
    float c1[3] = { s15[0]*invN, s15[1]*invN, s15[2]*invN };
    float c2[3] = { s15[3]*invN, s15[4]*invN, s15[5]*invN };
    // H[r][c] = sum s_r d_c - N c1_r c2_c ; M = H^T ; R = polar(M)
    float M[9];
    #pragma unroll
    for (int i = 0; i < 3; i++)
        #pragma unroll
        for (int j = 0; j < 3; j++)
            M[3*i+j] = s15[6+3*j+i] - (float)NPTS * c1[j] * c2[i];
    polar3(M, R);
    t[0] = c2[0] - (R[0]*c1[0] + R[1]*c1[1] + R[2]*c1[2]);
    t[1] = c2[1] - (R[3]*c1[0] + R[4]*c1[1] + R[5]*c1[2]);
    t[2] = c2[2] - (R[6]*c1[0] + R[7]*c1[1] + R[8]*c1[2]);
}

// ---------------------------------------------------------------------------
// Persistent kernel. Arrival: per-CTA private 128B line (data -> fence -> tag),
// polled in parallel by CTA0's threads 0..127 (one line each, zero contention,
// no atomics). CTA0 reduces+solves, publishes R,t, sets write-once release
// flag on its own line; others nanosleep-poll the flag.
// ---------------------------------------------------------------------------
__global__ void __launch_bounds__(TPB, 1)
icp_all(const float* __restrict__ p1, const float* __restrict__ p2,
        float* __restrict__ out)
{
    extern __shared__ unsigned char smem[];
    float4*             sj   = (float4*)(smem + SM_SJ);
    unsigned long long* key  = (unsigned long long*)(smem + SM_KEY);
    float*              mypc = (float*)(smem + SM_MYPC);
    float*              myp1 = (float*)(smem + SM_MYP1);
    float*              srt  = (float*)(smem + SM_SRT);
    float*              sred = (float*)(smem + SM_SRED);

    const int cta = blockIdx.x;
    const int tid = threadIdx.x;

    // load p2 (+ precomputed 0.5|q|^2) into shared; reused all iterations
    for (int j = tid; j < NPTS; j += TPB) {
        float qx = p2[j*3+0], qy = p2[j*3+1], qz = p2[j*3+2];
        sj[j] = make_float4(qx, qy, qz, 0.5f*fmaf(qx,qx,fmaf(qy,qy,qz*qz)));
    }
    if (tid < IPC) {
        int i = cta*IPC + tid;
        float x = p1[i*3+0], y = p1[i*3+1], z = p1[i*3+2];
        myp1[tid*3+0] = x; myp1[tid*3+1] = y; myp1[tid*3+2] = z;
        mypc[tid*3+0] = x; mypc[tid*3+1] = y; mypc[tid*3+2] = z;
    }
    __syncthreads();

    const int iblk  = tid & 7;        // 8 i-blocks of 4 points
    const int slice = tid >> 3;       // 64 j-slices of 64
    const int ib4   = iblk*4;

    for (int k = 0; k <= STEPS; k++) {
        // apply R_{k-1}, t_{k-1}: pc_k = R pc_{k-1} + t
        if (k > 0 && tid < IPC) {
            float x = mypc[tid*3+0], y = mypc[tid*3+1], z = mypc[tid*3+2];
            float nx = fmaf(srt[0],x, fmaf(srt[1],y, fmaf(srt[2],z, srt[9])));
            float ny = fmaf(srt[3],x, fmaf(srt[4],y, fmaf(srt[5],z, srt[10])));
            float nz = fmaf(srt[6],x, fmaf(srt[7],y, fmaf(srt[8],z, srt[11])));
            mypc[tid*3+0] = nx; mypc[tid*3+1] = ny; mypc[tid*3+2] = nz;
        }
        __syncthreads();

        if (k < STEPS) {
            // --- NN: 4 i-points x 64 j per thread, score = |q|^2/2 - p.q ---
            float x0=mypc[(ib4+0)*3+0], y0=mypc[(ib4+0)*3+1], z0=mypc[(ib4+0)*3+2];
            float x1=mypc[(ib4+1)*3+0], y1=mypc[(ib4+1)*3+1], z1=mypc[(ib4+1)*3+2];
            float x2=mypc[(ib4+2)*3+0], y2=mypc[(ib4+2)*3+1], z2=mypc[(ib4+2)*3+2];
            float x3=mypc[(ib4+3)*3+0], y3=mypc[(ib4+3)*3+1], z3=mypc[(ib4+3)*3+2];

            float b0=3.4028235e38f, b1=b0, b2=b0, b3=b0;
            int   j0=0, j1=0, j2=0, j3=0;
            const int jbeg = slice*JPS;
            #pragma unroll 8
            for (int jj = jbeg; jj < jbeg + JPS; jj++) {
                float4 q = sj[jj];
                float s0 = fmaf(-x0,q.x, fmaf(-y0,q.y, fmaf(-z0,q.z, q.w)));
                float s1 = fmaf(-x1,q.x, fmaf(-y1,q.y, fmaf(-z1,q.z, q.w)));
                float s2 = fmaf(-x2,q.x, fmaf(-y2,q.y, fmaf(-z2,q.z, q.w)));
                float s3 = fmaf(-x3,q.x, fmaf(-y3,q.y, fmaf(-z3,q.z, q.w)));
                if (s0 < b0) { b0 = s0; j0 = jj; }   // strict <: first index on ties
                if (s1 < b1) { b1 = s1; j1 = jj; }
                if (s2 < b2) { b2 = s2; j2 = jj; }
                if (s3 < b3) { b3 = s3; j3 = jj; }
            }
            key[slice*32 + ib4+0] = ((unsigned long long)fkey(b0) << 32) | (unsigned)j0;
            key[slice*32 + ib4+1] = ((unsigned long long)fkey(b1) << 32) | (unsigned)j1;
            key[slice*32 + ib4+2] = ((unsigned long long)fkey(b2) << 32) | (unsigned)j2;
            key[slice*32 + ib4+3] = ((unsigned long long)fkey(b3) << 32) | (unsigned)j3;
            __syncthreads();
        }

        // --- per-CTA covariance partials (warp 0) + private-line arrive ---
        if (tid < 32) {
            float sx, sy, sz, dx, dy, dz;
            if (k < STEPS) {
                unsigned long long best = key[tid];
                #pragma unroll 8
                for (int s2 = 1; s2 < NSL; s2++) {
                    unsigned long long v = key[s2*32 + tid];
                    if (v < best) best = v;   // (score, j) lexicographic: first-index ties
                }
                const int idx = (int)(unsigned)(best & 0xFFFFFFFFu);
                float4 q = sj[idx];
                dx = q.x; dy = q.y; dz = q.z;
                sx = mypc[tid*3+0]; sy = mypc[tid*3+1]; sz = mypc[tid*3+2];
            } else {
                sx = myp1[tid*3+0]; sy = myp1[tid*3+1]; sz = myp1[tid*3+2];
                dx = mypc[tid*3+0]; dy = mypc[tid*3+1]; dz = mypc[tid*3+2];
            }
            float a[15];
            a[0]=sx; a[1]=sy; a[2]=sz; a[3]=dx; a[4]=dy; a[5]=dz;
            a[6]=sx*dx; a[7]=sx*dy; a[8]=sx*dz;
            a[9]=sy*dx; a[10]=sy*dy; a[11]=sy*dz;
            a[12]=sz*dx; a[13]=sz*dy; a[14]=sz*dz;
            wred15(a);
            if (tid == 0) {
                volatile float* line = g_arr[k][cta];
                #pragma unroll
                for (int q = 0; q < 15; q++) line[q] = a[q];
                __threadfence();
                *(volatile int*)&g_arr[k][cta][15] = 1;   // tag (own line only)
            }
        }

        // --- CTA0: parallel poll of 128 private tag lines, reduce, solve ---
        if (cta == 0) {
            if (tid < NCTA) {
                volatile int* tp = (volatile int*)&g_arr[k][tid][15];
                while (*tp == 0) { }
            }
            __syncthreads();
            __threadfence();
            {
                float a[15];
                if (tid < NCTA) {
                    volatile float* gp = g_arr[k][tid];
                    #pragma unroll
                    for (int q = 0; q < 15; q++) a[q] = gp[q];
                    wred15(a);
                    if ((tid & 31) == 0) {
                        #pragma unroll
                        for (int q = 0; q < 15; q++) sred[(tid>>5)*15 + q] = a[q];
                    }
                }
            }
            __syncthreads();
            if (tid == 0) {
                float R[9], t[3];
                solve_from_sred(sred, R, t);
                if (k < STEPS) {
                    volatile float* grt = g_RT;
                    #pragma unroll
                    for (int q = 0; q < 9; q++) { srt[q] = R[q]; grt[q] = R[q]; }
                    srt[9]=t[0];  grt[9]  = t[0];
                    srt[10]=t[1]; grt[10] = t[1];
                    srt[11]=t[2]; grt[11] = t[2];
                    __threadfence();
                    ((volatile int*)g_sync)[48] = k + 1;   // release (own line)
                } else {
                    out[0]=R[0]; out[1]=R[1]; out[2]=R[2];  out[3]=t[0];
                    out[4]=R[3]; out[5]=R[4]; out[6]=R[5];  out[7]=t[1];
                    out[8]=R[6]; out[9]=R[7]; out[10]=R[8]; out[11]=t[2];
                }
            }
            __syncthreads();
        } else if (k < STEPS) {
            // --- other CTAs: wait for release, pick up R,t ---
            if (tid == 0) {
                while (((volatile int*)g_sync)[48] < k + 1) __nanosleep(16);
            }
            __syncthreads();
            __threadfence();
            if (tid < 12) srt[tid] = ((volatile float*)g_RT)[tid];
            __syncthreads();
        }
    }
}

extern "C" void kernel_launch(void* const* d_in, const int* in_sizes, int n_in,
                              void* d_out, int out_size)
{
    const float* p1 = (const float*)d_in[0];
    const float* p2 = (const float*)d_in[1];
    float* out = (float*)d_out;

    int* SYNC;
    float* ARR;
    cudaGetSymbolAddress((void**)&SYNC, g_sync);
    cudaGetSymbolAddress((void**)&ARR,  g_arr);
    cudaMemsetAsync(SYNC, 0, 64*sizeof(int), 0);
    cudaMemsetAsync(ARR,  0, (STEPS+1)*NCTA*32*sizeof(float), 0);

    static int attr_set = 0;
    if (!attr_set) {
        cudaFuncSetAttribute(icp_all, cudaFuncAttributeMaxDynamicSharedMemorySize,
                             SM_TOTAL);
        attr_set = 1;
    }
    icp_all<<<NCTA, TPB, SM_TOTAL>>>(p1, p2, out);
}

// round 11
// speedup vs baseline: 1.1034x; 1.1034x over previous
#include <cuda_runtime.h>

#define NPTS  4096
#define NCTA  128
#define TPB   512
#define IPC   32          // i-points per CTA
#define NSL   64          // j-slices (64 j each)
#define JPS   (NPTS/NSL)  // 64
#define STEPS 10
#define NSIT  10          // Newton-Schulz iterations
#define NCNT  8           // arrival counters (16 CTAs each)

// shared memory layout (bytes)
#define SM_SJ    0                       // float4[4096]  = 65536
#define SM_KEY   (NPTS*16)               // u64[NSL][32]  = 16384
#define SM_MYPC  (SM_KEY + NSL*32*8)     // float[96]
#define SM_MYP1  (SM_MYPC + 96*4)        // float[96]
#define SM_SRT   (SM_MYP1 + 96*4)        // float[12] (+pad)
#define SM_SRED  (SM_SRT + 16*4)         // float[4][15]
#define SM_TOTAL (SM_SRED + 4*15*4 + 64)

// global scratch (no allocations allowed)
__device__ float g_part[NCTA][16];
__device__ float g_RT[12];
__device__ int   g_cnt[NCNT][32];   // 8 monotone arrival counters, one per 128B line
__device__ int   g_sync[64];        // [48] release flag (k+1)

__device__ __forceinline__ unsigned int fkey(float f) {
    unsigned int u = __float_as_uint(f);
    return (u & 0x80000000u) ? ~u : (u | 0x80000000u);
}

// release-increment: orders all prior stores (the partials) before the add,
// no L1-flushing CCTL.IVALL (unlike __threadfence()+atomicAdd).
__device__ __forceinline__ void arrive_release(int* ctr) {
    asm volatile("red.release.gpu.global.add.u32 [%0], 1;" :: "l"(ctr) : "memory");
}

// ---------------------------------------------------------------------------
// Newton-Schulz polar: Q = orthogonal polar factor of M (3x3, det(M)>0).
// ---------------------------------------------------------------------------
__device__ __forceinline__ void polar3(const float M[9], float Q[9])
{
    float f2 = 0.f;
    #pragma unroll
    for (int q = 0; q < 9; q++) f2 = fmaf(M[q], M[q], f2);
    float inv = rsqrtf(f2);
    float X[9];
    #pragma unroll
    for (int q = 0; q < 9; q++) X[q] = M[q]*inv;

    #pragma unroll
    for (int it = 0; it < NSIT; it++) {
        float W[9];   // W = X^T X
        #pragma unroll
        for (int i = 0; i < 3; i++)
            #pragma unroll
            for (int j = 0; j < 3; j++)
                W[3*i+j] = fmaf(X[0+i], X[0+j],
                           fmaf(X[3+i], X[3+j], X[6+i]*X[6+j]));
        float Y[9];   // Y = X W
        #pragma unroll
        for (int i = 0; i < 3; i++)
            #pragma unroll
            for (int j = 0; j < 3; j++)
                Y[3*i+j] = fmaf(X[3*i+0], W[0+j],
                           fmaf(X[3*i+1], W[3+j], X[3*i+2]*W[6+j]));
        #pragma unroll
        for (int q = 0; q < 9; q++) X[q] = fmaf(1.5f, X[q], -0.5f*Y[q]);
    }
    #pragma unroll
    for (int q = 0; q < 9; q++) Q[q] = X[q];
}

// warp-reduce 15 accumulators (full warp, fixed order -> deterministic)
__device__ __forceinline__ void wred15(float a[15]) {
    #pragma unroll
    for (int q = 0; q < 15; q++)
        #pragma unroll
        for (int off = 16; off; off >>= 1)
            a[q] += __shfl_down_sync(0xffffffffu, a[q], off);
}

// solve from reduced sums (sred[4][15] in smem) -> R[9], t[3]
__device__ __forceinline__ void solve_from_sred(const float* sred,
                                                float R[9], float t[3])
{
    float s15[15];
    #pragma unroll
    for (int q = 0; q < 15; q++)
        s15[q] = (sred[q] + sred[15+q]) + (sred[30+q] + sred[45+q]);
    const float invN = 1.0f/NPTS;
    float c1[3] = { s15[0]*invN, s15[1]*invN, s15[2]*invN };
    float c2[3] = { s15[3]*invN, s15[4]*invN, s15[5]*invN };
    // H[r][c] = sum s_r d_c - N c1_r c2_c ; M = H^T ; R = polar(M)
    float M[9];
    #pragma unroll
    for (int i = 0; i < 3; i++)
        #pragma unroll
        for (int j = 0; j < 3; j++)
            M[3*i+j] = s15[6+3*j+i] - (float)NPTS * c1[j] * c2[i];
    polar3(M, R);
    t[0] = c2[0] - (R[0]*c1[0] + R[1]*c1[1] + R[2]*c1[2]);
    t[1] = c2[1] - (R[3]*c1[0] + R[4]*c1[1] + R[5]*c1[2]);
    t[2] = c2[2] - (R[6]*c1[0] + R[7]*c1[1] + R[8]*c1[2]);
}

// ---------------------------------------------------------------------------
// Persistent kernel: all STEPS iterations + final solve. grid=NCTA, block=TPB.
// Arrival: 8 split monotone counters (release-red, 16 CTAs each); CTA0
// threads 0..7 poll one counter each. CTA0 reduces+solves, publishes R,t,
// sets write-once release flag on its own line; others nanosleep-poll it.
// ---------------------------------------------------------------------------
__global__ void __launch_bounds__(TPB, 1)
icp_all(const float* __restrict__ p1, const float* __restrict__ p2,
        float* __restrict__ out)
{
    extern __shared__ unsigned char smem[];
    float4*             sj   = (float4*)(smem + SM_SJ);
    unsigned long long* key  = (unsigned long long*)(smem + SM_KEY);
    float*              mypc = (float*)(smem + SM_MYPC);
    float*              myp1 = (float*)(smem + SM_MYP1);
    float*              srt  = (float*)(smem + SM_SRT);
    float*              sred = (float*)(smem + SM_SRED);

    const int cta = blockIdx.x;
    const int tid = threadIdx.x;

    // load p2 (+ precomputed 0.5|q|^2) into shared; reused all iterations
    for (int j = tid; j < NPTS; j += TPB) {
        float qx = p2[j*3+0], qy = p2[j*3+1], qz = p2[j*3+2];
        sj[j] = make_float4(qx, qy, qz, 0.5f*fmaf(qx,qx,fmaf(qy,qy,qz*qz)));
    }
    if (tid < IPC) {
        int i = cta*IPC + tid;
        float x = p1[i*3+0], y = p1[i*3+1], z = p1[i*3+2];
        myp1[tid*3+0] = x; myp1[tid*3+1] = y; myp1[tid*3+2] = z;
        mypc[tid*3+0] = x; mypc[tid*3+1] = y; mypc[tid*3+2] = z;
    }
    __syncthreads();

    const int iblk  = tid & 7;        // 8 i-blocks of 4 points
    const int slice = tid >> 3;       // 64 j-slices of 64
    const int ib4   = iblk*4;

    for (int k = 0; k <= STEPS; k++) {
        // apply R_{k-1}, t_{k-1}: pc_k = R pc_{k-1} + t
        if (k > 0 && tid < IPC) {
            float x = mypc[tid*3+0], y = mypc[tid*3+1], z = mypc[tid*3+2];
            float nx = fmaf(srt[0],x, fmaf(srt[1],y, fmaf(srt[2],z, srt[9])));
            float ny = fmaf(srt[3],x, fmaf(srt[4],y, fmaf(srt[5],z, srt[10])));
            float nz = fmaf(srt[6],x, fmaf(srt[7],y, fmaf(srt[8],z, srt[11])));
            mypc[tid*3+0] = nx; mypc[tid*3+1] = ny; mypc[tid*3+2] = nz;
        }
        __syncthreads();

        if (k < STEPS) {
            // --- NN: 4 i-points x 64 j per thread, score = |q|^2/2 - p.q ---
            float x0=mypc[(ib4+0)*3+0], y0=mypc[(ib4+0)*3+1], z0=mypc[(ib4+0)*3+2];
            float x1=mypc[(ib4+1)*3+0], y1=mypc[(ib4+1)*3+1], z1=mypc[(ib4+1)*3+2];
            float x2=mypc[(ib4+2)*3+0], y2=mypc[(ib4+2)*3+1], z2=mypc[(ib4+2)*3+2];
            float x3=mypc[(ib4+3)*3+0], y3=mypc[(ib4+3)*3+1], z3=mypc[(ib4+3)*3+2];

            float b0=3.4028235e38f, b1=b0, b2=b0, b3=b0;
            int   j0=0, j1=0, j2=0, j3=0;
            const int jbeg = slice*JPS;
            #pragma unroll 8
            for (int jj = jbeg; jj < jbeg + JPS; jj++) {
                float4 q = sj[jj];
                float s0 = fmaf(-x0,q.x, fmaf(-y0,q.y, fmaf(-z0,q.z, q.w)));
                float s1 = fmaf(-x1,q.x, fmaf(-y1,q.y, fmaf(-z1,q.z, q.w)));
                float s2 = fmaf(-x2,q.x, fmaf(-y2,q.y, fmaf(-z2,q.z, q.w)));
                float s3 = fmaf(-x3,q.x, fmaf(-y3,q.y, fmaf(-z3,q.z, q.w)));
                if (s0 < b0) { b0 = s0; j0 = jj; }   // strict <: first index on ties
                if (s1 < b1) { b1 = s1; j1 = jj; }
                if (s2 < b2) { b2 = s2; j2 = jj; }
                if (s3 < b3) { b3 = s3; j3 = jj; }
            }
            key[slice*32 + ib4+0] = ((unsigned long long)fkey(b0) << 32) | (unsigned)j0;
            key[slice*32 + ib4+1] = ((unsigned long long)fkey(b1) << 32) | (unsigned)j1;
            key[slice*32 + ib4+2] = ((unsigned long long)fkey(b2) << 32) | (unsigned)j2;
            key[slice*32 + ib4+3] = ((unsigned long long)fkey(b3) << 32) | (unsigned)j3;
            __syncthreads();
        }

        // --- per-CTA covariance partials (warp 0) + split-counter arrive ---
        if (tid < 32) {
            float sx, sy, sz, dx, dy, dz;
            if (k < STEPS) {
                unsigned long long best = key[tid];
                #pragma unroll 8
                for (int s2 = 1; s2 < NSL; s2++) {
                    unsigned long long v = key[s2*32 + tid];
                    if (v < best) best = v;   // (score, j) lexicographic: first-index ties
                }
                const int idx = (int)(unsigned)(best & 0xFFFFFFFFu);
                float4 q = sj[idx];
                dx = q.x; dy = q.y; dz = q.z;
                sx = mypc[tid*3+0]; sy = mypc[tid*3+1]; sz = mypc[tid*3+2];
            } else {
                sx = myp1[tid*3+0]; sy = myp1[tid*3+1]; sz = myp1[tid*3+2];
                dx = mypc[tid*3+0]; dy = mypc[tid*3+1]; dz = mypc[tid*3+2];
            }
            float a[15];
            a[0]=sx; a[1]=sy; a[2]=sz; a[3]=dx; a[4]=dy; a[5]=dz;
            a[6]=sx*dx; a[7]=sx*dy; a[8]=sx*dz;
            a[9]=sy*dx; a[10]=sy*dy; a[11]=sy*dz;
            a[12]=sz*dx; a[13]=sz*dy; a[14]=sz*dz;
            wred15(a);
            if (tid == 0) {
                volatile float* gp = g_part[cta];
                #pragma unroll
                for (int q = 0; q < 15; q++) gp[q] = a[q];
                arrive_release(&g_cnt[cta & (NCNT-1)][0]);  // release: partials then +1
            }
        }

        // --- CTA0: poll 8 split counters (monotone target), reduce, solve ---
        if (cta == 0) {
            if (tid < NCNT) {
                const int target = (NCTA/NCNT) * (k + 1);
                volatile int* cp = &g_cnt[tid][0];
                while (*cp < target) __nanosleep(16);
            }
            __syncthreads();
            __threadfence();
            {
                float a[15];
                if (tid < NCTA) {
                    volatile float* gp = g_part[tid];
                    #pragma unroll
                    for (int q = 0; q < 15; q++) a[q] = gp[q];
                    wred15(a);
                    if ((tid & 31) == 0) {
                        #pragma unroll
                        for (int q = 0; q < 15; q++) sred[(tid>>5)*15 + q] = a[q];
                    }
                }
            }
            __syncthreads();
            if (tid == 0) {
                float R[9], t[3];
                solve_from_sred(sred, R, t);
                if (k < STEPS) {
                    volatile float* grt = g_RT;
                    #pragma unroll
                    for (int q = 0; q < 9; q++) { srt[q] = R[q]; grt[q] = R[q]; }
                    srt[9]=t[0];  grt[9]  = t[0];
                    srt[10]=t[1]; grt[10] = t[1];
                    srt[11]=t[2]; grt[11] = t[2];
                    __threadfence();
                    ((volatile int*)g_sync)[48] = k + 1;   // release (own line)
                } else {
                    out[0]=R[0]; out[1]=R[1]; out[2]=R[2];  out[3]=t[0];
                    out[4]=R[3]; out[5]=R[4]; out[6]=R[5];  out[7]=t[1];
                    out[8]=R[6]; out[9]=R[7]; out[10]=R[8]; out[11]=t[2];
                }
            }
            __syncthreads();
        } else if (k < STEPS) {
            // --- other CTAs: wait for release, pick up R,t (no IVALL fence:
            //     g_RT reached L2 before the flag did; volatile reads hit L2) ---
            if (tid == 0) {
                while (((volatile int*)g_sync)[48] < k + 1) __nanosleep(16);
            }
            __syncthreads();
            if (tid < 12) srt[tid] = ((volatile float*)g_RT)[tid];
            __syncthreads();
        }
    }
}

extern "C" void kernel_launch(void* const* d_in, const int* in_sizes, int n_in,
                              void* d_out, int out_size)
{
    const float* p1 = (const float*)d_in[0];
    const float* p2 = (const float*)d_in[1];
    float* out = (float*)d_out;

    int *SYNC, *CNT;
    cudaGetSymbolAddress((void**)&SYNC, g_sync);
    cudaGetSymbolAddress((void**)&CNT,  g_cnt);
    cudaMemsetAsync(SYNC, 0, 64*sizeof(int), 0);
    cudaMemsetAsync(CNT,  0, NCNT*32*sizeof(int), 0);

    static int attr_set = 0;
    if (!attr_set) {
        cudaFuncSetAttribute(icp_all, cudaFuncAttributeMaxDynamicSharedMemorySize,
                             SM_TOTAL);
        attr_set = 1;
    }
    icp_all<<<NCTA, TPB, SM_TOTAL>>>(p1, p2, out);
}

// round 12
// speedup vs baseline: 2.0295x; 1.8394x over previous
#include <cuda_runtime.h>

#define NPTS  4096
#define NCTA  128
#define TPB   512
#define IPC   32          // i-points per CTA
#define NSL   64          // j-slices (64 j each)
#define JPS   (NPTS/NSL)  // 64
#define STEPS 10
#define NSIT  8           // Newton-Schulz iterations
#define NCNT  8           // arrival counters (16 CTAs each)
#define GPC   (NCTA/NCNT) // 16
#define DONEFLAG 64       // > any k+1

// shared memory layout (bytes)
#define SM_SJ    0                       // float4[4096]  = 65536
#define SM_KEY   (NPTS*16)               // u64[NSL][32]  = 16384
#define SM_MYPC  (SM_KEY + NSL*32*8)     // float[96]
#define SM_MYP1  (SM_MYPC + 96*4)        // float[96]
#define SM_SRT   (SM_MYP1 + 96*4)        // float[12] (+pad)
#define SM_SRED  (SM_SRT + 16*4)         // float[4][15] (+pad)
#define SM_PREV  (SM_SRED + 64*4)        // int[32]
#define SM_CHG   (SM_PREV + 32*4)        // int[8]
#define SM_FLG   (SM_CHG + 8*4)          // int[4]
#define SM_TOTAL (SM_FLG + 16 + 64)

// global scratch (no allocations allowed)
__device__ float g_part[NCTA][16];
__device__ float g_RT[12];
__device__ int   g_cnt[NCNT][32];   // word0: arrivals (monotone), word1: changed (monotone)
__device__ int   g_sync[64];        // [48] release flag

__device__ __forceinline__ unsigned int fkey(float f) {
    unsigned int u = __float_as_uint(f);
    return (u & 0x80000000u) ? ~u : (u | 0x80000000u);
}

// release-increment: orders ALL prior stores/reds before the add; no IVALL.
__device__ __forceinline__ void arrive_release(int* ctr) {
    asm volatile("red.release.gpu.global.add.u32 [%0], 1;" :: "l"(ctr) : "memory");
}
__device__ __forceinline__ void add_relaxed(int* ctr) {
    asm volatile("red.relaxed.gpu.global.add.u32 [%0], 1;" :: "l"(ctr) : "memory");
}
// release store: orders prior stores (g_RT) before the flag; no IVALL.
__device__ __forceinline__ void st_release(int* p, int v) {
    asm volatile("st.release.gpu.global.u32 [%0], %1;" :: "l"(p), "r"(v) : "memory");
}

// ---------------------------------------------------------------------------
// Newton-Schulz polar: Q = orthogonal polar factor of M (3x3, det(M)>0).
// ---------------------------------------------------------------------------
__device__ __forceinline__ void polar3(const float M[9], float Q[9])
{
    float f2 = 0.f;
    #pragma unroll
    for (int q = 0; q < 9; q++) f2 = fmaf(M[q], M[q], f2);
    float inv = rsqrtf(f2);
    float X[9];
    #pragma unroll
    for (int q = 0; q < 9; q++) X[q] = M[q]*inv;

    #pragma unroll
    for (int it = 0; it < NSIT; it++) {
        float W[9];   // W = X^T X
        #pragma unroll
        for (int i = 0; i < 3; i++)
            #pragma unroll
            for (int j = 0; j < 3; j++)
                W[3*i+j] = fmaf(X[0+i], X[0+j],
                           fmaf(X[3+i], X[3+j], X[6+i]*X[6+j]));
        float Y[9];   // Y = X W
        #pragma unroll
        for (int i = 0; i < 3; i++)
            #pragma unroll
            for (int j = 0; j < 3; j++)
                Y[3*i+j] = fmaf(X[3*i+0], W[0+j],
                           fmaf(X[3*i+1], W[3+j], X[3*i+2]*W[6+j]));
        #pragma unroll
        for (int q = 0; q < 9; q++) X[q] = fmaf(1.5f, X[q], -0.5f*Y[q]);
    }
    #pragma unroll
    for (int q = 0; q < 9; q++) Q[q] = X[q];
}

// warp-reduce 15 accumulators (full warp, fixed order -> deterministic)
__device__ __forceinline__ void wred15(float a[15]) {
    #pragma unroll
    for (int q = 0; q < 15; q++)
        #pragma unroll
        for (int off = 16; off; off >>= 1)
            a[q] += __shfl_down_sync(0xffffffffu, a[q], off);
}

// solve from reduced sums (sred[4][15] in smem) -> R[9], t[3]
__device__ __forceinline__ void solve_from_sred(const float* sred,
                                                float R[9], float t[3])
{
    float s15[15];
    #pragma unroll
    for (int q = 0; q < 15; q++)
        s15[q] = (sred[q] + sred[15+q]) + (sred[30+q] + sred[45+q]);
    const float invN = 1.0f/NPTS;
    float c1[3] = { s15[0]*invN, s15[1]*invN, s15[2]*invN };
    float c2[3] = { s15[3]*invN, s15[4]*invN, s15[5]*invN };
    float M[9];
    #pragma unroll
    for (int i = 0; i < 3; i++)
        #pragma unroll
        for (int j = 0; j < 3; j++)
            M[3*i+j] = s15[6+3*j+i] - (float)NPTS * c1[j] * c2[i];
    polar3(M, R);
    t[0] = c2[0] - (R[0]*c1[0] + R[1]*c1[1] + R[2]*c1[2]);
    t[1] = c2[1] - (R[3]*c1[0] + R[4]*c1[1] + R[5]*c1[2]);
    t[2] = c2[2] - (R[6]*c1[0] + R[7]*c1[1] + R[8]*c1[2]);
}

// ---------------------------------------------------------------------------
// Persistent kernel with exact convergence skip. grid=NCTA, block=TPB.
// ---------------------------------------------------------------------------
__global__ void __launch_bounds__(TPB, 1)
icp_all(const float* __restrict__ p1, const float* __restrict__ p2,
        float* __restrict__ out)
{
    extern __shared__ unsigned char smem[];
    float4*             sj   = (float4*)(smem + SM_SJ);
    unsigned long long* key  = (unsigned long long*)(smem + SM_KEY);
    float*              mypc = (float*)(smem + SM_MYPC);
    float*              myp1 = (float*)(smem + SM_MYP1);
    float*              srt  = (float*)(smem + SM_SRT);
    float*              sred = (float*)(smem + SM_SRED);
    int*                previdx = (int*)(smem + SM_PREV);
    int*                schg = (int*)(smem + SM_CHG);
    int*                sflg = (int*)(smem + SM_FLG);

    const int cta = blockIdx.x;
    const int tid = threadIdx.x;

    for (int j = tid; j < NPTS; j += TPB) {
        float qx = p2[j*3+0], qy = p2[j*3+1], qz = p2[j*3+2];
        sj[j] = make_float4(qx, qy, qz, 0.5f*fmaf(qx,qx,fmaf(qy,qy,qz*qz)));
    }
    if (tid < IPC) {
        int i = cta*IPC + tid;
        float x = p1[i*3+0], y = p1[i*3+1], z = p1[i*3+2];
        myp1[tid*3+0] = x; myp1[tid*3+1] = y; myp1[tid*3+2] = z;
        mypc[tid*3+0] = x; mypc[tid*3+1] = y; mypc[tid*3+2] = z;
        previdx[tid] = -1;
    }
    __syncthreads();

    const int iblk  = tid & 7;        // 8 i-blocks of 4 points
    const int slice = tid >> 3;       // 64 j-slices of 64
    const int ib4   = iblk*4;

    int arrived = 0;
    int prevChangedTotal = 0;   // CTA0 tid0 only
    bool done = false;

    for (int k = 0; k < STEPS; k++) {
        // --- NN on current mypc: 4 i-points x 64 j, score = |q|^2/2 - p.q ---
        {
            float x0=mypc[(ib4+0)*3+0], y0=mypc[(ib4+0)*3+1], z0=mypc[(ib4+0)*3+2];
            float x1=mypc[(ib4+1)*3+0], y1=mypc[(ib4+1)*3+1], z1=mypc[(ib4+1)*3+2];
            float x2=mypc[(ib4+2)*3+0], y2=mypc[(ib4+2)*3+1], z2=mypc[(ib4+2)*3+2];
            float x3=mypc[(ib4+3)*3+0], y3=mypc[(ib4+3)*3+1], z3=mypc[(ib4+3)*3+2];

            float b0=3.4028235e38f, b1=b0, b2=b0, b3=b0;
            int   j0=0, j1=0, j2=0, j3=0;
            const int jbeg = slice*JPS;
            #pragma unroll 8
            for (int jj = jbeg; jj < jbeg + JPS; jj++) {
                float4 q = sj[jj];
                float s0 = fmaf(-x0,q.x, fmaf(-y0,q.y, fmaf(-z0,q.z, q.w)));
                float s1 = fmaf(-x1,q.x, fmaf(-y1,q.y, fmaf(-z1,q.z, q.w)));
                float s2 = fmaf(-x2,q.x, fmaf(-y2,q.y, fmaf(-z2,q.z, q.w)));
                float s3 = fmaf(-x3,q.x, fmaf(-y3,q.y, fmaf(-z3,q.z, q.w)));
                if (s0 < b0) { b0 = s0; j0 = jj; }   // strict <: first index on ties
                if (s1 < b1) { b1 = s1; j1 = jj; }
                if (s2 < b2) { b2 = s2; j2 = jj; }
                if (s3 < b3) { b3 = s3; j3 = jj; }
            }
            key[slice*32 + ib4+0] = ((unsigned long long)fkey(b0) << 32) | (unsigned)j0;
            key[slice*32 + ib4+1] = ((unsigned long long)fkey(b1) << 32) | (unsigned)j1;
            key[slice*32 + ib4+2] = ((unsigned long long)fkey(b2) << 32) | (unsigned)j2;
            key[slice*32 + ib4+3] = ((unsigned long long)fkey(b3) << 32) | (unsigned)j3;
        }
        __syncthreads();

        // --- warp0: argmin combine + changed-detect + partials + arrive ---
        if (tid < 32) {
            unsigned long long best = key[tid];
            #pragma unroll 8
            for (int s2 = 1; s2 < NSL; s2++) {
                unsigned long long v = key[s2*32 + tid];
                if (v < best) best = v;   // (score, j) lexicographic: first-index ties
            }
            const int idx = (int)(unsigned)(best & 0xFFFFFFFFu);
            int changed = (idx != previdx[tid]);
            previdx[tid] = idx;
            unsigned cm = __ballot_sync(0xffffffffu, changed);

            float4 q = sj[idx];
            float dx = q.x, dy = q.y, dz = q.z;
            float sx = mypc[tid*3+0], sy = mypc[tid*3+1], sz = mypc[tid*3+2];
            float a[15];
            a[0]=sx; a[1]=sy; a[2]=sz; a[3]=dx; a[4]=dy; a[5]=dz;
            a[6]=sx*dx; a[7]=sx*dy; a[8]=sx*dz;
            a[9]=sy*dx; a[10]=sy*dy; a[11]=sy*dz;
            a[12]=sz*dx; a[13]=sz*dy; a[14]=sz*dz;
            wred15(a);
            if (tid == 0) {
                volatile float* gp = g_part[cta];
                #pragma unroll
                for (int q2 = 0; q2 < 15; q2++) gp[q2] = a[q2];
                if (cm) add_relaxed(&g_cnt[cta & (NCNT-1)][1]);  // changed-count (same line)
                arrive_release(&g_cnt[cta & (NCNT-1)][0]);       // orders partials + changed
            }
        }
        arrived++;

        if (cta == 0) {
            // --- detect arrivals, read changed counts ---
            if (tid < NCNT) {
                volatile int* cp = &g_cnt[tid][0];
                while (*cp < GPC*arrived) __nanosleep(16);
                schg[tid] = *(volatile int*)&g_cnt[tid][1];
            }
            __syncthreads();
            {
                float a[15];
                if (tid < NCTA) {
                    volatile float* gp = g_part[tid];
                    #pragma unroll
                    for (int q = 0; q < 15; q++) a[q] = gp[q];
                    wred15(a);
                    if ((tid & 31) == 0) {
                        #pragma unroll
                        for (int q = 0; q < 15; q++) sred[(tid>>5)*15 + q] = a[q];
                    }
                }
            }
            __syncthreads();
            if (tid == 0) {
                int total = ((schg[0]+schg[1])+(schg[2]+schg[3]))
                          + ((schg[4]+schg[5])+(schg[6]+schg[7]));
                int newly = total - prevChangedTotal;
                prevChangedTotal = total;
                if (newly == 0) {
                    // matches identical to last iteration -> R=I,t=0 exactly;
                    // all remaining iterations are no-ops. Skip them.
                    sflg[0] = 1;
                    st_release(&g_sync[48], DONEFLAG);
                } else {
                    float R[9], t[3];
                    solve_from_sred(sred, R, t);
                    #pragma unroll
                    for (int q = 0; q < 9; q++) srt[q] = R[q];
                    srt[9]=t[0]; srt[10]=t[1]; srt[11]=t[2];
                    volatile float* grt = g_RT;
                    #pragma unroll
                    for (int q = 0; q < 9; q++) grt[q] = R[q];
                    grt[9]=t[0]; grt[10]=t[1]; grt[11]=t[2];
                    st_release(&g_sync[48], k + 1);   // orders g_RT before flag
                    sflg[0] = 0;
                }
            }
            __syncthreads();
            done = (sflg[0] != 0);
        } else {
            if (tid == 0) {
                volatile int* fp = &((volatile int*)g_sync)[48];
                while (*fp < k + 1) __nanosleep(16);
                sflg[0] = *fp;
            }
            __syncthreads();
            if (sflg[0] >= DONEFLAG) {
                done = true;
            } else if (tid < 12) {
                srt[tid] = ((volatile float*)g_RT)[tid];
            }
            __syncthreads();
        }

        if (done) break;

        // --- apply R_k, t_k: pc <- R pc + t ---
        if (tid < IPC) {
            float x = mypc[tid*3+0], y = mypc[tid*3+1], z = mypc[tid*3+2];
            float nx = fmaf(srt[0],x, fmaf(srt[1],y, fmaf(srt[2],z, srt[9])));
            float ny = fmaf(srt[3],x, fmaf(srt[4],y, fmaf(srt[5],z, srt[10])));
            float nz = fmaf(srt[6],x, fmaf(srt[7],y, fmaf(srt[8],z, srt[11])));
            mypc[tid*3+0] = nx; mypc[tid*3+1] = ny; mypc[tid*3+2] = nz;
        }
        __syncthreads();
    }

    // --- final solve: Kabsch(p1 -> pc_final) ---
    if (tid < 32) {
        float sx = myp1[tid*3+0], sy = myp1[tid*3+1], sz = myp1[tid*3+2];
        float dx = mypc[tid*3+0], dy = mypc[tid*3+1], dz = mypc[tid*3+2];
        float a[15];
        a[0]=sx; a[1]=sy; a[2]=sz; a[3]=dx; a[4]=dy; a[5]=dz;
        a[6]=sx*dx; a[7]=sx*dy; a[8]=sx*dz;
        a[9]=sy*dx; a[10]=sy*dy; a[11]=sy*dz;
        a[12]=sz*dx; a[13]=sz*dy; a[14]=sz*dz;
        wred15(a);
        if (tid == 0) {
            volatile float* gp = g_part[cta];
            #pragma unroll
            for (int q = 0; q < 15; q++) gp[q] = a[q];
            arrive_release(&g_cnt[cta & (NCNT-1)][0]);
        }
    }
    arrived++;

    if (cta != 0) return;

    if (tid < NCNT) {
        volatile int* cp = &g_cnt[tid][0];
        while (*cp < GPC*arrived) __nanosleep(16);
    }
    __syncthreads();
    {
        float a[15];
        if (tid < NCTA) {
            volatile float* gp = g_part[tid];
            #pragma unroll
            for (int q = 0; q < 15; q++) a[q] = gp[q];
            wred15(a);
            if ((tid & 31) == 0) {
                #pragma unroll
                for (int q = 0; q < 15; q++) sred[(tid>>5)*15 + q] = a[q];
            }
        }
    }
    __syncthreads();
    if (tid == 0) {
        float R[9], t[3];
        solve_from_sred(sred, R, t);
        out[0]=R[0]; out[1]=R[1]; out[2]=R[2];  out[3]=t[0];
        out[4]=R[3]; out[5]=R[4]; out[6]=R[5];  out[7]=t[1];
        out[8]=R[6]; out[9]=R[7]; out[10]=R[8]; out[11]=t[2];
    }
}

extern "C" void kernel_launch(void* const* d_in, const int* in_sizes, int n_in,
                              void* d_out, int out_size)
{
    const float* p1 = (const float*)d_in[0];
    const float* p2 = (const float*)d_in[1];
    float* out = (float*)d_out;

    int *SYNC, *CNT;
    cudaGetSymbolAddress((void**)&SYNC, g_sync);
    cudaGetSymbolAddress((void**)&CNT,  g_cnt);
    cudaMemsetAsync(SYNC, 0, 64*sizeof(int), 0);
    cudaMemsetAsync(CNT,  0, NCNT*32*sizeof(int), 0);

    static int attr_set = 0;
    if (!attr_set) {
        cudaFuncSetAttribute(icp_all, cudaFuncAttributeMaxDynamicSharedMemorySize,
                             SM_TOTAL);
        attr_set = 1;
    }
    icp_all<<<NCTA, TPB, SM_TOTAL>>>(p1, p2, out);
}